// round 5
// baseline (speedup 1.0000x reference)
#include <cuda_runtime.h>
#include <cuda_bf16.h>
#include <cstdint>

// LNSLinear == y = x @ W^T + bias (log-domain max/rescale is an exact identity).
// R4: same split-bf16 HMMA math as R3 (hi*hi + lo*hi + hi*lo, fp32 accum),
// restructured for occupancy: 256 CTAs (32x32 tiles) x 8 warps with
// CTA-internal split-K (warps 0-3: K[0,256), warps 4-7: K[256,512)),
// SMEM reduce + bias in-kernel. R3 had 1 warp/SMSP; this has ~3.5.

namespace {
constexpr int Mdim = 512, Ndim = 512, Kdim = 512;
constexpr int TM = 32, TN = 32, KC = 64;
constexpr int NITER = 4;                   // chunks per K-half
// Per-chunk stage: AH | AL | BH | BL, each 32 rows x 128B (KC bf16)
constexpr int PLANE = 32 * 128;            // 4096
constexpr int OFF_AH = 0, OFF_AL = PLANE, OFF_BH = 2 * PLANE, OFF_BL = 3 * PLANE;
constexpr int STAGE = 4 * PLANE;           // 16384
// 4 stages: [half][buf]  -> (h*2+b)*STAGE
constexpr int SMEM_TOTAL = 4 * STAGE;      // 65536
}

// bf16 planes: [0]=x_hi, [1]=x_lo, [2]=w_hi, [3]=w_lo
__device__ __nv_bfloat16 g_planes[4][Mdim * Kdim];

__device__ __forceinline__ uint32_t smem_u32(const void* p) {
    uint32_t a;
    asm("{ .reg .u64 t; cvta.to.shared.u64 t, %1; cvt.u32.u64 %0, t; }"
        : "=r"(a) : "l"(p));
    return a;
}

__device__ __forceinline__ void cp16(uint32_t dst, const void* src) {
    asm volatile("cp.async.cg.shared.global [%0], [%1], 16;"
                 :: "r"(dst), "l"(src));
}

__device__ __forceinline__ void ldm_x4(uint32_t* r, uint32_t addr) {
    asm volatile(
        "ldmatrix.sync.aligned.m8n8.x4.shared.b16 {%0, %1, %2, %3}, [%4];"
        : "=r"(r[0]), "=r"(r[1]), "=r"(r[2]), "=r"(r[3]) : "r"(addr));
}

__device__ __forceinline__ void mma16816(float* d, const uint32_t* a,
                                         const uint32_t* b) {
    asm volatile(
        "mma.sync.aligned.m16n8k16.row.col.f32.bf16.bf16.f32 "
        "{%0, %1, %2, %3}, {%4, %5, %6, %7}, {%8, %9}, {%0, %1, %2, %3};"
        : "+f"(d[0]), "+f"(d[1]), "+f"(d[2]), "+f"(d[3])
        : "r"(a[0]), "r"(a[1]), "r"(a[2]), "r"(a[3]), "r"(b[0]), "r"(b[1]));
}

// ---------------- Kernel 1: fp32 -> bf16 hi/lo planes ----------------
__global__ __launch_bounds__(256) void convert_hilo(
    const float* __restrict__ x, const float* __restrict__ w) {
    const int idx = blockIdx.x * 256 + threadIdx.x;   // float4 id, 131072 total
    const bool isx = idx < 65536;
    const int local = idx & 65535;
    const float4 v = reinterpret_cast<const float4*>(isx ? x : w)[local];
    __nv_bfloat162 h01 = __float22bfloat162_rn(make_float2(v.x, v.y));
    __nv_bfloat162 h23 = __float22bfloat162_rn(make_float2(v.z, v.w));
    const float2 f01 = __bfloat1622float2(h01);
    const float2 f23 = __bfloat1622float2(h23);
    __nv_bfloat162 l01 = __float22bfloat162_rn(make_float2(v.x - f01.x, v.y - f01.y));
    __nv_bfloat162 l23 = __float22bfloat162_rn(make_float2(v.z - f23.x, v.w - f23.y));
    const int p = isx ? 0 : 2;
    reinterpret_cast<uint2*>(g_planes[p])[local] =
        make_uint2(*reinterpret_cast<uint32_t*>(&h01),
                   *reinterpret_cast<uint32_t*>(&h23));
    reinterpret_cast<uint2*>(g_planes[p + 1])[local] =
        make_uint2(*reinterpret_cast<uint32_t*>(&l01),
                   *reinterpret_cast<uint32_t*>(&l23));
}

// ---------------- Kernel 2: split-bf16 GEMM, split-K in-CTA ----------------
__global__ __launch_bounds__(256, 2) void lns_hmma_gemm(
    const float* __restrict__ bias, float* __restrict__ out) {
    extern __shared__ char smem[];
    const uint32_t sb = smem_u32(smem);
    const int t = threadIdx.x;
    const int wid = t >> 5;
    const int l = t & 31;
    const int m0 = blockIdx.y * TM;
    const int n0 = blockIdx.x * TN;

    const int h  = wid >> 2;          // K-half (0 or 1)
    const int w4 = wid & 3;           // warp within half
    const int wm = (w4 & 1) * 16;     // warp m offset in tile
    const int wn = (w4 >> 1) * 16;    // warp n offset in tile

    // Loader mapping: thread t -> row r = t>>3 (0..31), 16B col c16 = t&7.
    const int lr  = t >> 3;
    const int lc  = t & 7;
    const uint32_t ldst = (uint32_t)(lr * 128 + ((lc * 16) ^ ((lr & 7) * 16)));
    const size_t asrc0 = (size_t)(m0 + lr) * Kdim + lc * 8;
    const size_t bsrc0 = (size_t)(n0 + lr) * Kdim + lc * 8;

    auto load_iter = [&](int it, int buf) {
#pragma unroll
        for (int hh = 0; hh < 2; ++hh) {
            const int kb = (hh * NITER + it) * KC;
            const uint32_t s = sb + (uint32_t)(hh * 2 + buf) * STAGE + ldst;
            cp16(s + OFF_AH, &g_planes[0][asrc0 + kb]);
            cp16(s + OFF_AL, &g_planes[1][asrc0 + kb]);
            cp16(s + OFF_BH, &g_planes[2][bsrc0 + kb]);
            cp16(s + OFF_BL, &g_planes[3][bsrc0 + kb]);
        }
        asm volatile("cp.async.commit_group;" ::: "memory");
    };

    // ldmatrix per-lane addressing (same fragment scheme as R3, validated).
    const int a_row = wm + (l & 15);
    const uint32_t a_rb = (uint32_t)(a_row * 128);
    const uint32_t a_xr = (uint32_t)((a_row & 7) * 16);
    const uint32_t a_c0 = (uint32_t)((l >> 4) * 16);
    const int b_row = wn + (l & 7) + ((l >> 4) << 3);
    const uint32_t b_rb = (uint32_t)(b_row * 128);
    const uint32_t b_xr = (uint32_t)((b_row & 7) * 16);
    const uint32_t b_c0 = (uint32_t)(((l >> 3) & 1) * 16);

    float d[2][4];
#pragma unroll
    for (int i = 0; i < 2; ++i)
#pragma unroll
        for (int j = 0; j < 4; ++j) d[i][j] = 0.0f;

    load_iter(0, 0);

    for (int it = 0; it < NITER; ++it) {
        if (it < NITER - 1) {
            load_iter(it + 1, (it + 1) & 1);
            asm volatile("cp.async.wait_group 1;" ::: "memory");
        } else {
            asm volatile("cp.async.wait_group 0;" ::: "memory");
        }
        __syncthreads();

        const uint32_t s = sb + (uint32_t)(h * 2 + (it & 1)) * STAGE;
        const uint32_t ah_b = s + OFF_AH + a_rb;
        const uint32_t al_b = s + OFF_AL + a_rb;
        const uint32_t bh_b = s + OFF_BH + b_rb;
        const uint32_t bl_b = s + OFF_BL + b_rb;

#pragma unroll
        for (int ks = 0; ks < 4; ++ks) {
            const uint32_t cA = (uint32_t)(ks * 32) + a_c0;
            const uint32_t cB = (uint32_t)(ks * 32) + b_c0;
            uint32_t ah[4], al[4], bh[4], bl[4];
            ldm_x4(ah, ah_b + (cA ^ a_xr));
            ldm_x4(al, al_b + (cA ^ a_xr));
            ldm_x4(bh, bh_b + (cB ^ b_xr));
            ldm_x4(bl, bl_b + (cB ^ b_xr));
#pragma unroll
            for (int nt = 0; nt < 2; ++nt) {
                mma16816(d[nt], ah, bh + 2 * nt);   // hi*hi
                mma16816(d[nt], al, bh + 2 * nt);   // lo*hi
                mma16816(d[nt], ah, bl + 2 * nt);   // hi*lo
            }
        }
        __syncthreads();
    }

    // ---- Split-K reduce via SMEM (reuse stage 0), then bias + store ----
    // Layout: [w4][lane][8 floats]
    float* red = reinterpret_cast<float*>(smem) + (w4 * 32 + l) * 8;
    if (h == 1) {
#pragma unroll
        for (int nt = 0; nt < 2; ++nt)
#pragma unroll
            for (int j = 0; j < 4; ++j) red[nt * 4 + j] = d[nt][j];
    }
    __syncthreads();
    if (h == 0) {
        const int g  = l >> 2;
        const int tc = l & 3;
        const int row0 = m0 + wm + g;
#pragma unroll
        for (int nt = 0; nt < 2; ++nt) {
            const int col = n0 + wn + nt * 8 + tc * 2;
            const float2 bv = *reinterpret_cast<const float2*>(bias + col);
            float2 o0, o1;
            o0.x = d[nt][0] + red[nt * 4 + 0] + bv.x;
            o0.y = d[nt][1] + red[nt * 4 + 1] + bv.y;
            o1.x = d[nt][2] + red[nt * 4 + 2] + bv.x;
            o1.y = d[nt][3] + red[nt * 4 + 3] + bv.y;
            *reinterpret_cast<float2*>(out + (size_t)row0 * Ndim + col) = o0;
            *reinterpret_cast<float2*>(out + (size_t)(row0 + 8) * Ndim + col) = o1;
        }
    }
}

extern "C" void kernel_launch(void* const* d_in, const int* in_sizes, int n_in,
                              void* d_out, int out_size) {
    (void)in_sizes; (void)n_in; (void)out_size;
    const float* x    = (const float*)d_in[0];   // [512, 512]
    const float* w    = (const float*)d_in[1];   // [512, 512]
    const float* bias = (const float*)d_in[2];   // [512]
    float* out = (float*)d_out;                  // [512, 512] fp32

    convert_hilo<<<512, 256>>>(x, w);

    static bool attr_set = false;
    if (!attr_set) {
        cudaFuncSetAttribute(lns_hmma_gemm,
                             cudaFuncAttributeMaxDynamicSharedMemorySize,
                             SMEM_TOTAL);
        attr_set = true;
    }
    dim3 grid(Ndim / TN, Mdim / TM);             // 16 x 16 = 256 CTAs
    lns_hmma_gemm<<<grid, 256, SMEM_TOTAL>>>(bias, out);
}